// round 15
// baseline (speedup 1.0000x reference)
#include <cuda_runtime.h>
#include <cuda_fp16.h>
#include <math.h>
#include <stdint.h>

// GCN: out = relu(Agg(X@W1)+b1) -> relu(Agg(.@W2)+b2) -> @Wl + bl
// GEMM1: tf32 mma (fp32 X), writes fp16 messages.
// Agg: dst-CSR pull, coalesced edge fetch + shfl broadcast, fp32 accum,
//      fused self-loop+bias+relu, fp16 hidden out.
// GEMM2/cls: fp16 m16n8k16 mma (fp32 accum).
// CSR build overlapped with GEMM1 on a second stream.

#define N_NODES 100000
#define N_EDGES 1600000
#define F 128
#define NCLS 40

#define SCAN_CHUNK 512
#define NBLK_SCAN ((N_NODES + SCAN_CHUNK - 1) / SCAN_CHUNK)  // 196

// ---- scratch (device globals; allocation-free) ----
__device__ float  g_dinv[N_NODES];
__device__ int    g_cnt[N_NODES];
__device__ int    g_rowptr[N_NODES + 1];
__device__ int    g_cursor[N_NODES];
__device__ int    g_partial[NBLK_SCAN];
__device__ int2   g_epack[N_EDGES];             // (src, norm bits)
__device__ __half g_hbuf[(size_t)N_NODES * F];  // fp16 xw messages
__device__ __half g_hid[(size_t)N_NODES * F];   // fp16 hidden states

// ------------------------------------------------------------------
// CSR build
// ------------------------------------------------------------------
__global__ void hist_kernel(const int* __restrict__ dst) {
    int e = blockIdx.x * blockDim.x + threadIdx.x;
    if (e < N_EDGES) atomicAdd(&g_cnt[dst[e]], 1);
}

// fused: dinv + per-chunk sums
__global__ void __launch_bounds__(SCAN_CHUNK) dinv_partial_kernel() {
    __shared__ int s[SCAN_CHUNK];
    int t = threadIdx.x;
    int i = blockIdx.x * SCAN_CHUNK + t;
    int c = (i < N_NODES) ? g_cnt[i] : 0;
    if (i < N_NODES) g_dinv[i] = rsqrtf((float)c + 1.0f);  // +1 self loop
    s[t] = c;
    __syncthreads();
    for (int off = SCAN_CHUNK / 2; off > 0; off >>= 1) {
        if (t < off) s[t] += s[t + off];
        __syncthreads();
    }
    if (t == 0) g_partial[blockIdx.x] = s[0];
}

// per-chunk scan; each block computes its own base from the partials
__global__ void __launch_bounds__(SCAN_CHUNK) scan_write_kernel() {
    __shared__ int s[SCAN_CHUNK];
    __shared__ int base_sh;
    int t = threadIdx.x;
    int i = blockIdx.x * SCAN_CHUNK + t;
    int v = (i < N_NODES) ? g_cnt[i] : 0;
    s[t] = v;

    // block prefix over partials (each thread sums a strided subset, then
    // warp0 reduces via shared atomics-free tree in s? keep it simple:
    // thread t sums partials t, t+512, ... < blockIdx; then reduce via shfl)
    int part = 0;
    for (int b = t; b < blockIdx.x; b += SCAN_CHUNK) part += g_partial[b];
    // reduce 'part' across block into base_sh
    __syncthreads();
    // warp-level then smem reduce
    for (int off = 16; off > 0; off >>= 1)
        part += __shfl_down_sync(0xffffffffu, part, off);
    __shared__ int wsum[SCAN_CHUNK / 32];
    if ((t & 31) == 0) wsum[t >> 5] = part;
    __syncthreads();
    if (t == 0) {
        int b = 0;
#pragma unroll
        for (int w = 0; w < SCAN_CHUNK / 32; w++) b += wsum[w];
        base_sh = b;
    }
    __syncthreads();

    // Hillis-Steele inclusive scan of the chunk
    for (int off = 1; off < SCAN_CHUNK; off <<= 1) {
        int x = (t >= off) ? s[t - off] : 0;
        __syncthreads();
        s[t] += x;
        __syncthreads();
    }
    if (i < N_NODES) {
        int rp = base_sh + s[t] - v;
        g_rowptr[i] = rp;
        g_cursor[i] = rp;
    }
    if (i == N_NODES - 1) g_rowptr[N_NODES] = base_sh + s[t];
}

__global__ void scatter_kernel(const int* __restrict__ src,
                               const int* __restrict__ dst) {
    int e = blockIdx.x * blockDim.x + threadIdx.x;
    if (e >= N_EDGES) return;
    int s = src[e];
    int d = dst[e];
    float nm = g_dinv[s] * g_dinv[d];
    int pos = atomicAdd(&g_cursor[d], 1);
    g_epack[pos] = make_int2(s, __float_as_int(nm));
}

// ------------------------------------------------------------------
// tf32 GEMM (layer 1): C16[N,128] = A32[N,128] @ W[128,128], fp16 out
// ------------------------------------------------------------------
__device__ __forceinline__ uint32_t f2tf32(float f) {
    uint32_t u;
    asm("cvt.rna.tf32.f32 %0, %1;" : "=r"(u) : "f"(f));
    return u;
}

__device__ __forceinline__ uint32_t h2bits(__half2 h) {
    return *(uint32_t*)&h;
}

#define AS_STRIDE 36   // tf32: 32 k + pad
#define BS_STRIDE 132  // tf32: 128 n + pad

__global__ void __launch_bounds__(256) gemm_tf32_kernel(
    const float* __restrict__ A, const float* __restrict__ W,
    __half* __restrict__ C) {
    __shared__ uint32_t As[128 * AS_STRIDE];
    __shared__ uint32_t Bs[32 * BS_STRIDE];

    int tid = threadIdx.x;
    int lane = tid & 31;
    int warp = tid >> 5;
    int wr = warp >> 1;
    int wc = warp & 1;
    int g = lane >> 2;
    int tg = lane & 3;
    int row0 = blockIdx.x * 128;

    float acc[2][8][4];
#pragma unroll
    for (int tm = 0; tm < 2; tm++)
#pragma unroll
        for (int tn = 0; tn < 8; tn++)
#pragma unroll
            for (int c = 0; c < 4; c++) acc[tm][tn][c] = 0.0f;

#pragma unroll
    for (int kc = 0; kc < 4; kc++) {
#pragma unroll
        for (int i = 0; i < 4; i++) {
            int j = tid + i * 256;
            int r = j >> 3, k4 = j & 7;
            int grow = row0 + r;
            float4 v = make_float4(0.f, 0.f, 0.f, 0.f);
            if (grow < N_NODES)
                v = *(const float4*)(A + (size_t)grow * F + kc * 32 + k4 * 4);
            uint4 u;
            u.x = f2tf32(v.x); u.y = f2tf32(v.y);
            u.z = f2tf32(v.z); u.w = f2tf32(v.w);
            *(uint4*)(As + r * AS_STRIDE + k4 * 4) = u;
        }
#pragma unroll
        for (int i = 0; i < 4; i++) {
            int j = tid + i * 256;
            int kk = j >> 5, n4 = j & 31;
            float4 v = *(const float4*)(W + (size_t)(kc * 32 + kk) * 128 + n4 * 4);
            uint4 u;
            u.x = f2tf32(v.x); u.y = f2tf32(v.y);
            u.z = f2tf32(v.z); u.w = f2tf32(v.w);
            *(uint4*)(Bs + kk * BS_STRIDE + n4 * 4) = u;
        }
        __syncthreads();

#pragma unroll
        for (int k8 = 0; k8 < 4; k8++) {
            uint32_t a[2][4];
#pragma unroll
            for (int tm = 0; tm < 2; tm++) {
                int rbase = wr * 32 + tm * 16;
                const uint32_t* ap = As + k8 * 8 + tg;
                a[tm][0] = ap[(rbase + g) * AS_STRIDE];
                a[tm][1] = ap[(rbase + g + 8) * AS_STRIDE];
                a[tm][2] = ap[(rbase + g) * AS_STRIDE + 4];
                a[tm][3] = ap[(rbase + g + 8) * AS_STRIDE + 4];
            }
#pragma unroll
            for (int tn = 0; tn < 8; tn++) {
                int ncol = wc * 64 + tn * 8 + g;
                uint32_t b0 = Bs[(k8 * 8 + tg) * BS_STRIDE + ncol];
                uint32_t b1 = Bs[(k8 * 8 + tg + 4) * BS_STRIDE + ncol];
#pragma unroll
                for (int tm = 0; tm < 2; tm++) {
                    asm volatile(
                        "mma.sync.aligned.m16n8k8.row.col.f32.tf32.tf32.f32 "
                        "{%0,%1,%2,%3}, {%4,%5,%6,%7}, {%8,%9}, {%0,%1,%2,%3};"
                        : "+f"(acc[tm][tn][0]), "+f"(acc[tm][tn][1]),
                          "+f"(acc[tm][tn][2]), "+f"(acc[tm][tn][3])
                        : "r"(a[tm][0]), "r"(a[tm][1]), "r"(a[tm][2]),
                          "r"(a[tm][3]), "r"(b0), "r"(b1));
                }
            }
        }
        __syncthreads();
    }

#pragma unroll
    for (int tm = 0; tm < 2; tm++) {
#pragma unroll
        for (int tn = 0; tn < 8; tn++) {
            int r = row0 + wr * 32 + tm * 16 + g;
            int c = wc * 64 + tn * 8 + tg * 2;
            if (r < N_NODES)
                *(__half2*)(C + (size_t)r * F + c) =
                    __floats2half2_rn(acc[tm][tn][0], acc[tm][tn][1]);
            if (r + 8 < N_NODES)
                *(__half2*)(C + (size_t)(r + 8) * F + c) =
                    __floats2half2_rn(acc[tm][tn][2], acc[tm][tn][3]);
        }
    }
}

// ------------------------------------------------------------------
// fp16 GEMM (layer 2): C16[N,128] = A16[N,128] @ W[128,128]
// ------------------------------------------------------------------
#define AH_STRIDE 20   // u32 stride: 16 u32 (32 halves) + 4 pad
#define BH_STRIDE 132  // u32 stride: 128 n + pad (half2 pairs along k)

__global__ void __launch_bounds__(256) gemm_f16_kernel(
    const __half* __restrict__ A, const float* __restrict__ W,
    __half* __restrict__ C) {
    __shared__ uint32_t As[128 * AH_STRIDE];
    __shared__ uint32_t Bs[16 * BH_STRIDE];

    int tid = threadIdx.x;
    int lane = tid & 31;
    int warp = tid >> 5;
    int wr = warp >> 1;
    int wc = warp & 1;
    int g = lane >> 2;
    int tg = lane & 3;
    int row0 = blockIdx.x * 128;

    float acc[2][8][4];
#pragma unroll
    for (int tm = 0; tm < 2; tm++)
#pragma unroll
        for (int tn = 0; tn < 8; tn++)
#pragma unroll
            for (int c = 0; c < 4; c++) acc[tm][tn][c] = 0.0f;

#pragma unroll
    for (int kc = 0; kc < 4; kc++) {
#pragma unroll
        for (int i = 0; i < 2; i++) {
            int j = tid + i * 256;
            int r = j >> 2, q = j & 3;
            int grow = row0 + r;
            uint4 v = make_uint4(0, 0, 0, 0);
            if (grow < N_NODES)
                v = *(const uint4*)(A + (size_t)grow * F + kc * 32 + q * 8);
            *(uint2*)(As + r * AH_STRIDE + q * 4) = make_uint2(v.x, v.y);
            *(uint2*)(As + r * AH_STRIDE + q * 4 + 2) = make_uint2(v.z, v.w);
        }
#pragma unroll
        for (int i = 0; i < 8; i++) {
            int j = tid + i * 256;
            int k2 = j >> 7, n = j & 127;
            int krow = kc * 32 + k2 * 2;
            float w0 = W[(size_t)krow * 128 + n];
            float w1 = W[(size_t)(krow + 1) * 128 + n];
            Bs[k2 * BH_STRIDE + n] = h2bits(__floats2half2_rn(w0, w1));
        }
        __syncthreads();

#pragma unroll
        for (int s = 0; s < 2; s++) {
            uint32_t a[2][4];
#pragma unroll
            for (int tm = 0; tm < 2; tm++) {
                int rbase = wr * 32 + tm * 16;
                const uint32_t* ap = As + s * 8 + tg;
                a[tm][0] = ap[(rbase + g) * AH_STRIDE];
                a[tm][1] = ap[(rbase + g + 8) * AH_STRIDE];
                a[tm][2] = ap[(rbase + g) * AH_STRIDE + 4];
                a[tm][3] = ap[(rbase + g + 8) * AH_STRIDE + 4];
            }
#pragma unroll
            for (int tn = 0; tn < 8; tn++) {
                int ncol = wc * 64 + tn * 8 + g;
                uint32_t b0 = Bs[(s * 8 + tg) * BH_STRIDE + ncol];
                uint32_t b1 = Bs[(s * 8 + tg + 4) * BH_STRIDE + ncol];
#pragma unroll
                for (int tm = 0; tm < 2; tm++) {
                    asm volatile(
                        "mma.sync.aligned.m16n8k16.row.col.f32.f16.f16.f32 "
                        "{%0,%1,%2,%3}, {%4,%5,%6,%7}, {%8,%9}, {%0,%1,%2,%3};"
                        : "+f"(acc[tm][tn][0]), "+f"(acc[tm][tn][1]),
                          "+f"(acc[tm][tn][2]), "+f"(acc[tm][tn][3])
                        : "r"(a[tm][0]), "r"(a[tm][1]), "r"(a[tm][2]),
                          "r"(a[tm][3]), "r"(b0), "r"(b1));
                }
            }
        }
        __syncthreads();
    }

#pragma unroll
    for (int tm = 0; tm < 2; tm++) {
#pragma unroll
        for (int tn = 0; tn < 8; tn++) {
            int r = row0 + wr * 32 + tm * 16 + g;
            int c = wc * 64 + tn * 8 + tg * 2;
            if (r < N_NODES)
                *(__half2*)(C + (size_t)r * F + c) =
                    __floats2half2_rn(acc[tm][tn][0], acc[tm][tn][1]);
            if (r + 8 < N_NODES)
                *(__half2*)(C + (size_t)(r + 8) * F + c) =
                    __floats2half2_rn(acc[tm][tn][2], acc[tm][tn][3]);
        }
    }
}

// ------------------------------------------------------------------
// CSR pull aggregation: coalesced edge fetch + shfl broadcast.
// fp16 messages in, fp32 accum, fused self-loop+bias+relu, fp16 out.
// one warp per node; lane owns 4 halves.
// ------------------------------------------------------------------
__device__ __forceinline__ void acc_row(float4& acc, const __half* p, float nm) {
    uint2 u = *(const uint2*)p;
    __half2 h0 = *(__half2*)&u.x;
    __half2 h1 = *(__half2*)&u.y;
    float2 f0 = __half22float2(h0);
    float2 f1 = __half22float2(h1);
    acc.x += f0.x * nm; acc.y += f0.y * nm;
    acc.z += f1.x * nm; acc.w += f1.y * nm;
}

__global__ void __launch_bounds__(512) agg_csr_kernel(
    const __half* __restrict__ xw, __half* __restrict__ out,
    const float* __restrict__ bias) {
    int warp = (blockIdx.x * 512 + threadIdx.x) >> 5;
    int lane = threadIdx.x & 31;
    if (warp >= N_NODES) return;
    int node = warp;

    float di = g_dinv[node];
    float4 acc = make_float4(0.f, 0.f, 0.f, 0.f);

    // self loop
    acc_row(acc, xw + (size_t)node * F + lane * 4, di * di);

    int beg = g_rowptr[node];
    int end = g_rowptr[node + 1];

    for (int j = beg; j < end; j += 32) {
        int cnt = end - j;
        if (cnt > 32) cnt = 32;
        int2 p = make_int2(0, 0);
        if (lane < cnt) p = g_epack[j + lane];  // coalesced 256B per warp
        int t = 0;
        for (; t + 3 < cnt; t += 4) {
            int s0 = __shfl_sync(0xffffffffu, p.x, t);
            float n0 = __int_as_float(__shfl_sync(0xffffffffu, p.y, t));
            int s1 = __shfl_sync(0xffffffffu, p.x, t + 1);
            float n1 = __int_as_float(__shfl_sync(0xffffffffu, p.y, t + 1));
            int s2 = __shfl_sync(0xffffffffu, p.x, t + 2);
            float n2 = __int_as_float(__shfl_sync(0xffffffffu, p.y, t + 2));
            int s3 = __shfl_sync(0xffffffffu, p.x, t + 3);
            float n3 = __int_as_float(__shfl_sync(0xffffffffu, p.y, t + 3));
            acc_row(acc, xw + (size_t)s0 * F + lane * 4, n0);
            acc_row(acc, xw + (size_t)s1 * F + lane * 4, n1);
            acc_row(acc, xw + (size_t)s2 * F + lane * 4, n2);
            acc_row(acc, xw + (size_t)s3 * F + lane * 4, n3);
        }
        for (; t < cnt; t++) {
            int s0 = __shfl_sync(0xffffffffu, p.x, t);
            float n0 = __int_as_float(__shfl_sync(0xffffffffu, p.y, t));
            acc_row(acc, xw + (size_t)s0 * F + lane * 4, n0);
        }
    }

    float4 bb = ((const float4*)bias)[lane];
    acc.x = fmaxf(acc.x + bb.x, 0.f);
    acc.y = fmaxf(acc.y + bb.y, 0.f);
    acc.z = fmaxf(acc.z + bb.z, 0.f);
    acc.w = fmaxf(acc.w + bb.w, 0.f);
    __half2 h0 = __floats2half2_rn(acc.x, acc.y);
    __half2 h1 = __floats2half2_rn(acc.z, acc.w);
    *(uint2*)(out + (size_t)node * F + lane * 4) =
        make_uint2(h2bits(h0), h2bits(h1));
}

// ------------------------------------------------------------------
// fp16 classifier: out32[N,40] = A16[N,128] @ Wl[128,40] + bl
// ------------------------------------------------------------------
#define WH_STRIDE 44  // u32 stride: 40 n + pad

__global__ void __launch_bounds__(256) cls_f16_kernel(
    const __half* __restrict__ A, const float* __restrict__ Wl,
    const float* __restrict__ bl, float* __restrict__ out) {
    __shared__ uint32_t As[128 * AH_STRIDE];
    __shared__ uint32_t Ws[64 * WH_STRIDE];

    int tid = threadIdx.x;
    int lane = tid & 31;
    int warp = tid >> 5;
    int g = lane >> 2;
    int tg = lane & 3;
    int row0 = blockIdx.x * 128;

    for (int j = tid; j < 64 * 40; j += 256) {
        int k2 = j / 40, n = j % 40;
        float w0 = Wl[(size_t)(k2 * 2) * NCLS + n];
        float w1 = Wl[(size_t)(k2 * 2 + 1) * NCLS + n];
        Ws[k2 * WH_STRIDE + n] = h2bits(__floats2half2_rn(w0, w1));
    }

    float acc[5][4];
#pragma unroll
    for (int tn = 0; tn < 5; tn++)
#pragma unroll
        for (int c = 0; c < 4; c++) acc[tn][c] = 0.0f;

#pragma unroll
    for (int kc = 0; kc < 4; kc++) {
#pragma unroll
        for (int i = 0; i < 2; i++) {
            int j = tid + i * 256;
            int r = j >> 2, q = j & 3;
            int grow = row0 + r;
            uint4 v = make_uint4(0, 0, 0, 0);
            if (grow < N_NODES)
                v = *(const uint4*)(A + (size_t)grow * F + kc * 32 + q * 8);
            *(uint2*)(As + r * AH_STRIDE + q * 4) = make_uint2(v.x, v.y);
            *(uint2*)(As + r * AH_STRIDE + q * 4 + 2) = make_uint2(v.z, v.w);
        }
        __syncthreads();

#pragma unroll
        for (int s = 0; s < 2; s++) {
            int rbase = warp * 16;
            const uint32_t* ap = As + s * 8 + tg;
            uint32_t a0 = ap[(rbase + g) * AH_STRIDE];
            uint32_t a1 = ap[(rbase + g + 8) * AH_STRIDE];
            uint32_t a2 = ap[(rbase + g) * AH_STRIDE + 4];
            uint32_t a3 = ap[(rbase + g + 8) * AH_STRIDE + 4];
            int k2base = kc * 16 + s * 8;
#pragma unroll
            for (int tn = 0; tn < 5; tn++) {
                int ncol = tn * 8 + g;
                uint32_t b0 = Ws[(k2base + tg) * WH_STRIDE + ncol];
                uint32_t b1 = Ws[(k2base + tg + 4) * WH_STRIDE + ncol];
                asm volatile(
                    "mma.sync.aligned.m16n8k16.row.col.f32.f16.f16.f32 "
                    "{%0,%1,%2,%3}, {%4,%5,%6,%7}, {%8,%9}, {%0,%1,%2,%3};"
                    : "+f"(acc[tn][0]), "+f"(acc[tn][1]),
                      "+f"(acc[tn][2]), "+f"(acc[tn][3])
                    : "r"(a0), "r"(a1), "r"(a2), "r"(a3), "r"(b0), "r"(b1));
            }
        }
        __syncthreads();
    }

#pragma unroll
    for (int tn = 0; tn < 5; tn++) {
        int r = row0 + warp * 16 + g;
        int c = tn * 8 + tg * 2;
        float2 bb = *(const float2*)(bl + c);
        if (r < N_NODES)
            *(float2*)(out + (size_t)r * NCLS + c) =
                make_float2(acc[tn][0] + bb.x, acc[tn][1] + bb.y);
        if (r + 8 < N_NODES)
            *(float2*)(out + (size_t)(r + 8) * NCLS + c) =
                make_float2(acc[tn][2] + bb.x, acc[tn][3] + bb.y);
    }
}

// ------------------------------------------------------------------
extern "C" void kernel_launch(void* const* d_in, const int* in_sizes, int n_in,
                              void* d_out, int out_size) {
    const float* X  = (const float*)d_in[0];
    const int*   EI = (const int*)d_in[1];   // [2, E]: src | dst
    const float* W1 = (const float*)d_in[2];
    const float* b1 = (const float*)d_in[3];
    const float* W2 = (const float*)d_in[4];
    const float* b2 = (const float*)d_in[5];
    const float* Wl = (const float*)d_in[6];
    const float* bl = (const float*)d_in[7];
    float* out = (float*)d_out;

    const int* src = EI;
    const int* dst = EI + N_EDGES;

    __half *hbuf, *hid;
    int* cntp;
    cudaGetSymbolAddress((void**)&hbuf, g_hbuf);
    cudaGetSymbolAddress((void**)&hid, g_hid);
    cudaGetSymbolAddress((void**)&cntp, g_cnt);

    static cudaStream_t s2 = nullptr;
    static cudaEvent_t evF = nullptr, evJ = nullptr;
    if (s2 == nullptr) {
        cudaStreamCreateWithFlags(&s2, cudaStreamNonBlocking);
        cudaEventCreateWithFlags(&evF, cudaEventDisableTiming);
        cudaEventCreateWithFlags(&evJ, cudaEventDisableTiming);
    }

    const int T = 256;
    int nblk_edges = (N_EDGES + T - 1) / T;
    int nblk_gemm  = (N_NODES + 127) / 128;
    int nblk_agg   = (N_NODES * 32 + 511) / 512;

    // ---- fork: CSR build + norm on s2, GEMM1 on main stream ----
    cudaEventRecord(evF, 0);
    cudaStreamWaitEvent(s2, evF, 0);

    cudaMemsetAsync(cntp, 0, N_NODES * sizeof(int), s2);
    hist_kernel<<<nblk_edges, T, 0, s2>>>(dst);
    dinv_partial_kernel<<<NBLK_SCAN, SCAN_CHUNK, 0, s2>>>();
    scan_write_kernel<<<NBLK_SCAN, SCAN_CHUNK, 0, s2>>>();
    scatter_kernel<<<nblk_edges, T, 0, s2>>>(src, dst);
    cudaEventRecord(evJ, s2);

    gemm_tf32_kernel<<<nblk_gemm, T>>>(X, W1, hbuf);

    // ---- join ----
    cudaStreamWaitEvent(0, evJ, 0);

    // ---- layer 1 agg ----
    agg_csr_kernel<<<nblk_agg, 512>>>(hbuf, hid, b1);

    // ---- layer 2 ----
    gemm_f16_kernel<<<nblk_gemm, T>>>(hid, W2, hbuf);
    agg_csr_kernel<<<nblk_agg, 512>>>(hbuf, hid, b2);

    // ---- classifier ----
    cls_f16_kernel<<<nblk_gemm, T>>>(hid, Wl, bl, out);
}

// round 17
// speedup vs baseline: 1.0366x; 1.0366x over previous
#include <cuda_runtime.h>
#include <cuda_fp16.h>
#include <math.h>
#include <stdint.h>

// GCN: out = relu(Agg(X@W1)+b1) -> relu(Agg(.@W2)+b2) -> @Wl + bl
// GEMM1: tf32 mma (fp32 X), writes fp16 messages.
// Agg: dst-CSR pull, packed (src,norm) int2 loads (R14 form), fp32 accum,
//      fused self-loop+bias+relu, fp16 hidden out.
// GEMM2/cls: fp16 m16n8k16 mma (fp32 accum).
// CSR build (rank-then-place, atomic-free placement) overlapped with GEMM1.

#define N_NODES 100000
#define N_EDGES 1600000
#define F 128
#define NCLS 40

#define SCAN_CHUNK 512
#define NBLK_SCAN ((N_NODES + SCAN_CHUNK - 1) / SCAN_CHUNK)  // 196

// ---- scratch (device globals; allocation-free) ----
__device__ float  g_dinv[N_NODES];
__device__ int    g_cnt[N_NODES];
__device__ int    g_rowptr[N_NODES + 1];
__device__ int    g_rank[N_EDGES];
__device__ int    g_partial[NBLK_SCAN];
__device__ int2   g_epack[N_EDGES];             // (src, norm bits)
__device__ __half g_hbuf[(size_t)N_NODES * F];  // fp16 xw messages
__device__ __half g_hid[(size_t)N_NODES * F];   // fp16 hidden states

// ------------------------------------------------------------------
// CSR build: hist+rank, scan, atomic-free placement
// ------------------------------------------------------------------
__global__ void hist_rank_kernel(const int* __restrict__ dst) {
    int e = blockIdx.x * blockDim.x + threadIdx.x;
    if (e < N_EDGES) g_rank[e] = atomicAdd(&g_cnt[dst[e]], 1);
}

// fused: dinv + per-chunk sums
__global__ void __launch_bounds__(SCAN_CHUNK) dinv_partial_kernel() {
    __shared__ int s[SCAN_CHUNK];
    int t = threadIdx.x;
    int i = blockIdx.x * SCAN_CHUNK + t;
    int c = (i < N_NODES) ? g_cnt[i] : 0;
    if (i < N_NODES) g_dinv[i] = rsqrtf((float)c + 1.0f);  // +1 self loop
    s[t] = c;
    __syncthreads();
    for (int off = SCAN_CHUNK / 2; off > 0; off >>= 1) {
        if (t < off) s[t] += s[t + off];
        __syncthreads();
    }
    if (t == 0) g_partial[blockIdx.x] = s[0];
}

// per-chunk scan; each block computes its own base from the partials
__global__ void __launch_bounds__(SCAN_CHUNK) scan_write_kernel() {
    __shared__ int s[SCAN_CHUNK];
    __shared__ int base_sh;
    __shared__ int wsum[SCAN_CHUNK / 32];
    int t = threadIdx.x;
    int i = blockIdx.x * SCAN_CHUNK + t;
    int v = (i < N_NODES) ? g_cnt[i] : 0;
    s[t] = v;

    int part = 0;
    for (int b = t; b < blockIdx.x; b += SCAN_CHUNK) part += g_partial[b];
    __syncthreads();
    for (int off = 16; off > 0; off >>= 1)
        part += __shfl_down_sync(0xffffffffu, part, off);
    if ((t & 31) == 0) wsum[t >> 5] = part;
    __syncthreads();
    if (t == 0) {
        int b = 0;
#pragma unroll
        for (int w = 0; w < SCAN_CHUNK / 32; w++) b += wsum[w];
        base_sh = b;
    }
    __syncthreads();

    for (int off = 1; off < SCAN_CHUNK; off <<= 1) {
        int x = (t >= off) ? s[t - off] : 0;
        __syncthreads();
        s[t] += x;
        __syncthreads();
    }
    if (i < N_NODES) g_rowptr[i] = base_sh + s[t] - v;
    if (i == N_NODES - 1) g_rowptr[N_NODES] = base_sh + s[t];
}

// atomic-free placement: pos = rowptr[dst] + rank
__global__ void place_kernel(const int* __restrict__ src,
                             const int* __restrict__ dst) {
    int e = blockIdx.x * blockDim.x + threadIdx.x;
    if (e >= N_EDGES) return;
    int s = src[e];
    int d = dst[e];
    float nm = g_dinv[s] * g_dinv[d];
    int pos = g_rowptr[d] + g_rank[e];
    g_epack[pos] = make_int2(s, __float_as_int(nm));
}

// ------------------------------------------------------------------
// tf32 GEMM (layer 1): C16[N,128] = A32[N,128] @ W[128,128], fp16 out
// ------------------------------------------------------------------
__device__ __forceinline__ uint32_t f2tf32(float f) {
    uint32_t u;
    asm("cvt.rna.tf32.f32 %0, %1;" : "=r"(u) : "f"(f));
    return u;
}

__device__ __forceinline__ uint32_t h2bits(__half2 h) {
    return *(uint32_t*)&h;
}

#define AS_STRIDE 36   // tf32: 32 k + pad
#define BS_STRIDE 132  // tf32: 128 n + pad

__global__ void __launch_bounds__(256) gemm_tf32_kernel(
    const float* __restrict__ A, const float* __restrict__ W,
    __half* __restrict__ C) {
    __shared__ uint32_t As[128 * AS_STRIDE];
    __shared__ uint32_t Bs[32 * BS_STRIDE];

    int tid = threadIdx.x;
    int lane = tid & 31;
    int warp = tid >> 5;
    int wr = warp >> 1;
    int wc = warp & 1;
    int g = lane >> 2;
    int tg = lane & 3;
    int row0 = blockIdx.x * 128;

    float acc[2][8][4];
#pragma unroll
    for (int tm = 0; tm < 2; tm++)
#pragma unroll
        for (int tn = 0; tn < 8; tn++)
#pragma unroll
            for (int c = 0; c < 4; c++) acc[tm][tn][c] = 0.0f;

#pragma unroll
    for (int kc = 0; kc < 4; kc++) {
#pragma unroll
        for (int i = 0; i < 4; i++) {
            int j = tid + i * 256;
            int r = j >> 3, k4 = j & 7;
            int grow = row0 + r;
            float4 v = make_float4(0.f, 0.f, 0.f, 0.f);
            if (grow < N_NODES)
                v = *(const float4*)(A + (size_t)grow * F + kc * 32 + k4 * 4);
            uint4 u;
            u.x = f2tf32(v.x); u.y = f2tf32(v.y);
            u.z = f2tf32(v.z); u.w = f2tf32(v.w);
            *(uint4*)(As + r * AS_STRIDE + k4 * 4) = u;
        }
#pragma unroll
        for (int i = 0; i < 4; i++) {
            int j = tid + i * 256;
            int kk = j >> 5, n4 = j & 31;
            float4 v = *(const float4*)(W + (size_t)(kc * 32 + kk) * 128 + n4 * 4);
            uint4 u;
            u.x = f2tf32(v.x); u.y = f2tf32(v.y);
            u.z = f2tf32(v.z); u.w = f2tf32(v.w);
            *(uint4*)(Bs + kk * BS_STRIDE + n4 * 4) = u;
        }
        __syncthreads();

#pragma unroll
        for (int k8 = 0; k8 < 4; k8++) {
            uint32_t a[2][4];
#pragma unroll
            for (int tm = 0; tm < 2; tm++) {
                int rbase = wr * 32 + tm * 16;
                const uint32_t* ap = As + k8 * 8 + tg;
                a[tm][0] = ap[(rbase + g) * AS_STRIDE];
                a[tm][1] = ap[(rbase + g + 8) * AS_STRIDE];
                a[tm][2] = ap[(rbase + g) * AS_STRIDE + 4];
                a[tm][3] = ap[(rbase + g + 8) * AS_STRIDE + 4];
            }
#pragma unroll
            for (int tn = 0; tn < 8; tn++) {
                int ncol = wc * 64 + tn * 8 + g;
                uint32_t b0 = Bs[(k8 * 8 + tg) * BS_STRIDE + ncol];
                uint32_t b1 = Bs[(k8 * 8 + tg + 4) * BS_STRIDE + ncol];
#pragma unroll
                for (int tm = 0; tm < 2; tm++) {
                    asm volatile(
                        "mma.sync.aligned.m16n8k8.row.col.f32.tf32.tf32.f32 "
                        "{%0,%1,%2,%3}, {%4,%5,%6,%7}, {%8,%9}, {%0,%1,%2,%3};"
                        : "+f"(acc[tm][tn][0]), "+f"(acc[tm][tn][1]),
                          "+f"(acc[tm][tn][2]), "+f"(acc[tm][tn][3])
                        : "r"(a[tm][0]), "r"(a[tm][1]), "r"(a[tm][2]),
                          "r"(a[tm][3]), "r"(b0), "r"(b1));
                }
            }
        }
        __syncthreads();
    }

#pragma unroll
    for (int tm = 0; tm < 2; tm++) {
#pragma unroll
        for (int tn = 0; tn < 8; tn++) {
            int r = row0 + wr * 32 + tm * 16 + g;
            int c = wc * 64 + tn * 8 + tg * 2;
            if (r < N_NODES)
                *(__half2*)(C + (size_t)r * F + c) =
                    __floats2half2_rn(acc[tm][tn][0], acc[tm][tn][1]);
            if (r + 8 < N_NODES)
                *(__half2*)(C + (size_t)(r + 8) * F + c) =
                    __floats2half2_rn(acc[tm][tn][2], acc[tm][tn][3]);
        }
    }
}

// ------------------------------------------------------------------
// fp16 GEMM (layer 2): C16[N,128] = A16[N,128] @ W[128,128]
// ------------------------------------------------------------------
#define AH_STRIDE 20   // u32 stride: 16 u32 (32 halves) + 4 pad
#define BH_STRIDE 132  // u32 stride: 128 n + pad (half2 pairs along k)

__global__ void __launch_bounds__(256) gemm_f16_kernel(
    const __half* __restrict__ A, const float* __restrict__ W,
    __half* __restrict__ C) {
    __shared__ uint32_t As[128 * AH_STRIDE];
    __shared__ uint32_t Bs[16 * BH_STRIDE];

    int tid = threadIdx.x;
    int lane = tid & 31;
    int warp = tid >> 5;
    int wr = warp >> 1;
    int wc = warp & 1;
    int g = lane >> 2;
    int tg = lane & 3;
    int row0 = blockIdx.x * 128;

    float acc[2][8][4];
#pragma unroll
    for (int tm = 0; tm < 2; tm++)
#pragma unroll
        for (int tn = 0; tn < 8; tn++)
#pragma unroll
            for (int c = 0; c < 4; c++) acc[tm][tn][c] = 0.0f;

#pragma unroll
    for (int kc = 0; kc < 4; kc++) {
#pragma unroll
        for (int i = 0; i < 2; i++) {
            int j = tid + i * 256;
            int r = j >> 2, q = j & 3;
            int grow = row0 + r;
            uint4 v = make_uint4(0, 0, 0, 0);
            if (grow < N_NODES)
                v = *(const uint4*)(A + (size_t)grow * F + kc * 32 + q * 8);
            *(uint2*)(As + r * AH_STRIDE + q * 4) = make_uint2(v.x, v.y);
            *(uint2*)(As + r * AH_STRIDE + q * 4 + 2) = make_uint2(v.z, v.w);
        }
#pragma unroll
        for (int i = 0; i < 8; i++) {
            int j = tid + i * 256;
            int k2 = j >> 7, n = j & 127;
            int krow = kc * 32 + k2 * 2;
            float w0 = W[(size_t)krow * 128 + n];
            float w1 = W[(size_t)(krow + 1) * 128 + n];
            Bs[k2 * BH_STRIDE + n] = h2bits(__floats2half2_rn(w0, w1));
        }
        __syncthreads();

#pragma unroll
        for (int s = 0; s < 2; s++) {
            uint32_t a[2][4];
#pragma unroll
            for (int tm = 0; tm < 2; tm++) {
                int rbase = wr * 32 + tm * 16;
                const uint32_t* ap = As + s * 8 + tg;
                a[tm][0] = ap[(rbase + g) * AH_STRIDE];
                a[tm][1] = ap[(rbase + g + 8) * AH_STRIDE];
                a[tm][2] = ap[(rbase + g) * AH_STRIDE + 4];
                a[tm][3] = ap[(rbase + g + 8) * AH_STRIDE + 4];
            }
#pragma unroll
            for (int tn = 0; tn < 8; tn++) {
                int ncol = wc * 64 + tn * 8 + g;
                uint32_t b0 = Bs[(s * 8 + tg) * BH_STRIDE + ncol];
                uint32_t b1 = Bs[(s * 8 + tg + 4) * BH_STRIDE + ncol];
#pragma unroll
                for (int tm = 0; tm < 2; tm++) {
                    asm volatile(
                        "mma.sync.aligned.m16n8k16.row.col.f32.f16.f16.f32 "
                        "{%0,%1,%2,%3}, {%4,%5,%6,%7}, {%8,%9}, {%0,%1,%2,%3};"
                        : "+f"(acc[tm][tn][0]), "+f"(acc[tm][tn][1]),
                          "+f"(acc[tm][tn][2]), "+f"(acc[tm][tn][3])
                        : "r"(a[tm][0]), "r"(a[tm][1]), "r"(a[tm][2]),
                          "r"(a[tm][3]), "r"(b0), "r"(b1));
                }
            }
        }
        __syncthreads();
    }

#pragma unroll
    for (int tm = 0; tm < 2; tm++) {
#pragma unroll
        for (int tn = 0; tn < 8; tn++) {
            int r = row0 + wr * 32 + tm * 16 + g;
            int c = wc * 64 + tn * 8 + tg * 2;
            if (r < N_NODES)
                *(__half2*)(C + (size_t)r * F + c) =
                    __floats2half2_rn(acc[tm][tn][0], acc[tm][tn][1]);
            if (r + 8 < N_NODES)
                *(__half2*)(C + (size_t)(r + 8) * F + c) =
                    __floats2half2_rn(acc[tm][tn][2], acc[tm][tn][3]);
        }
    }
}

// ------------------------------------------------------------------
// CSR pull aggregation (R14 form): packed int2 broadcast loads.
// fp16 messages in, fp32 accum, fused self-loop+bias+relu, fp16 out.
// one warp per node; lane owns 4 halves.
// ------------------------------------------------------------------
__device__ __forceinline__ void acc_row(float4& acc, const __half* p, float nm) {
    uint2 u = *(const uint2*)p;
    __half2 h0 = *(__half2*)&u.x;
    __half2 h1 = *(__half2*)&u.y;
    float2 f0 = __half22float2(h0);
    float2 f1 = __half22float2(h1);
    acc.x += f0.x * nm; acc.y += f0.y * nm;
    acc.z += f1.x * nm; acc.w += f1.y * nm;
}

__global__ void __launch_bounds__(256) agg_csr_kernel(
    const __half* __restrict__ xw, __half* __restrict__ out,
    const float* __restrict__ bias) {
    int warp = (blockIdx.x * 256 + threadIdx.x) >> 5;
    int lane = threadIdx.x & 31;
    if (warp >= N_NODES) return;
    int node = warp;

    float di = g_dinv[node];
    float4 acc = make_float4(0.f, 0.f, 0.f, 0.f);

    // self loop
    acc_row(acc, xw + (size_t)node * F + lane * 4, di * di);

    int beg = g_rowptr[node];
    int end = g_rowptr[node + 1];

    int j = beg;
    for (; j + 3 < end; j += 4) {
        int2 p0 = g_epack[j];
        int2 p1 = g_epack[j + 1];
        int2 p2 = g_epack[j + 2];
        int2 p3 = g_epack[j + 3];
        acc_row(acc, xw + (size_t)p0.x * F + lane * 4, __int_as_float(p0.y));
        acc_row(acc, xw + (size_t)p1.x * F + lane * 4, __int_as_float(p1.y));
        acc_row(acc, xw + (size_t)p2.x * F + lane * 4, __int_as_float(p2.y));
        acc_row(acc, xw + (size_t)p3.x * F + lane * 4, __int_as_float(p3.y));
    }
    for (; j < end; j++) {
        int2 p0 = g_epack[j];
        acc_row(acc, xw + (size_t)p0.x * F + lane * 4, __int_as_float(p0.y));
    }

    float4 bb = ((const float4*)bias)[lane];
    acc.x = fmaxf(acc.x + bb.x, 0.f);
    acc.y = fmaxf(acc.y + bb.y, 0.f);
    acc.z = fmaxf(acc.z + bb.z, 0.f);
    acc.w = fmaxf(acc.w + bb.w, 0.f);
    __half2 h0 = __floats2half2_rn(acc.x, acc.y);
    __half2 h1 = __floats2half2_rn(acc.z, acc.w);
    *(uint2*)(out + (size_t)node * F + lane * 4) =
        make_uint2(h2bits(h0), h2bits(h1));
}

// ------------------------------------------------------------------
// fp16 classifier: out32[N,40] = A16[N,128] @ Wl[128,40] + bl
// ------------------------------------------------------------------
#define WH_STRIDE 44  // u32 stride: 40 n + pad

__global__ void __launch_bounds__(256) cls_f16_kernel(
    const __half* __restrict__ A, const float* __restrict__ Wl,
    const float* __restrict__ bl, float* __restrict__ out) {
    __shared__ uint32_t As[128 * AH_STRIDE];
    __shared__ uint32_t Ws[64 * WH_STRIDE];

    int tid = threadIdx.x;
    int lane = tid & 31;
    int warp = tid >> 5;
    int g = lane >> 2;
    int tg = lane & 3;
    int row0 = blockIdx.x * 128;

    for (int j = tid; j < 64 * 40; j += 256) {
        int k2 = j / 40, n = j % 40;
        float w0 = Wl[(size_t)(k2 * 2) * NCLS + n];
        float w1 = Wl[(size_t)(k2 * 2 + 1) * NCLS + n];
        Ws[k2 * WH_STRIDE + n] = h2bits(__floats2half2_rn(w0, w1));
    }

    float acc[5][4];
#pragma unroll
    for (int tn = 0; tn < 5; tn++)
#pragma unroll
        for (int c = 0; c < 4; c++) acc[tn][c] = 0.0f;

#pragma unroll
    for (int kc = 0; kc < 4; kc++) {
#pragma unroll
        for (int i = 0; i < 2; i++) {
            int j = tid + i * 256;
            int r = j >> 2, q = j & 3;
            int grow = row0 + r;
            uint4 v = make_uint4(0, 0, 0, 0);
            if (grow < N_NODES)
                v = *(const uint4*)(A + (size_t)grow * F + kc * 32 + q * 8);
            *(uint2*)(As + r * AH_STRIDE + q * 4) = make_uint2(v.x, v.y);
            *(uint2*)(As + r * AH_STRIDE + q * 4 + 2) = make_uint2(v.z, v.w);
        }
        __syncthreads();

#pragma unroll
        for (int s = 0; s < 2; s++) {
            int rbase = warp * 16;
            const uint32_t* ap = As + s * 8 + tg;
            uint32_t a0 = ap[(rbase + g) * AH_STRIDE];
            uint32_t a1 = ap[(rbase + g + 8) * AH_STRIDE];
            uint32_t a2 = ap[(rbase + g) * AH_STRIDE + 4];
            uint32_t a3 = ap[(rbase + g + 8) * AH_STRIDE + 4];
            int k2base = kc * 16 + s * 8;
#pragma unroll
            for (int tn = 0; tn < 5; tn++) {
                int ncol = tn * 8 + g;
                uint32_t b0 = Ws[(k2base + tg) * WH_STRIDE + ncol];
                uint32_t b1 = Ws[(k2base + tg + 4) * WH_STRIDE + ncol];
                asm volatile(
                    "mma.sync.aligned.m16n8k16.row.col.f32.f16.f16.f32 "
                    "{%0,%1,%2,%3}, {%4,%5,%6,%7}, {%8,%9}, {%0,%1,%2,%3};"
                    : "+f"(acc[tn][0]), "+f"(acc[tn][1]),
                      "+f"(acc[tn][2]), "+f"(acc[tn][3])
                    : "r"(a0), "r"(a1), "r"(a2), "r"(a3), "r"(b0), "r"(b1));
            }
        }
        __syncthreads();
    }

#pragma unroll
    for (int tn = 0; tn < 5; tn++) {
        int r = row0 + warp * 16 + g;
        int c = tn * 8 + tg * 2;
        float2 bb = *(const float2*)(bl + c);
        if (r < N_NODES)
            *(float2*)(out + (size_t)r * NCLS + c) =
                make_float2(acc[tn][0] + bb.x, acc[tn][1] + bb.y);
        if (r + 8 < N_NODES)
            *(float2*)(out + (size_t)(r + 8) * NCLS + c) =
                make_float2(acc[tn][2] + bb.x, acc[tn][3] + bb.y);
    }
}

// ------------------------------------------------------------------
extern "C" void kernel_launch(void* const* d_in, const int* in_sizes, int n_in,
                              void* d_out, int out_size) {
    const float* X  = (const float*)d_in[0];
    const int*   EI = (const int*)d_in[1];   // [2, E]: src | dst
    const float* W1 = (const float*)d_in[2];
    const float* b1 = (const float*)d_in[3];
    const float* W2 = (const float*)d_in[4];
    const float* b2 = (const float*)d_in[5];
    const float* Wl = (const float*)d_in[6];
    const float* bl = (const float*)d_in[7];
    float* out = (float*)d_out;

    const int* src = EI;
    const int* dst = EI + N_EDGES;

    __half *hbuf, *hid;
    int* cntp;
    cudaGetSymbolAddress((void**)&hbuf, g_hbuf);
    cudaGetSymbolAddress((void**)&hid, g_hid);
    cudaGetSymbolAddress((void**)&cntp, g_cnt);

    static cudaStream_t s2 = nullptr;
    static cudaEvent_t evF = nullptr, evJ = nullptr;
    if (s2 == nullptr) {
        cudaStreamCreateWithFlags(&s2, cudaStreamNonBlocking);
        cudaEventCreateWithFlags(&evF, cudaEventDisableTiming);
        cudaEventCreateWithFlags(&evJ, cudaEventDisableTiming);
    }

    const int T = 256;
    int nblk_edges = (N_EDGES + T - 1) / T;
    int nblk_gemm  = (N_NODES + 127) / 128;
    int nblk_agg   = (N_NODES * 32 + T - 1) / T;

    // ---- fork: CSR build + norm on s2, GEMM1 on main stream ----
    cudaEventRecord(evF, 0);
    cudaStreamWaitEvent(s2, evF, 0);

    cudaMemsetAsync(cntp, 0, N_NODES * sizeof(int), s2);
    hist_rank_kernel<<<nblk_edges, T, 0, s2>>>(dst);
    dinv_partial_kernel<<<NBLK_SCAN, SCAN_CHUNK, 0, s2>>>();
    scan_write_kernel<<<NBLK_SCAN, SCAN_CHUNK, 0, s2>>>();
    place_kernel<<<nblk_edges, T, 0, s2>>>(src, dst);
    cudaEventRecord(evJ, s2);

    gemm_tf32_kernel<<<nblk_gemm, T>>>(X, W1, hbuf);

    // ---- join ----
    cudaStreamWaitEvent(0, evJ, 0);

    // ---- layer 1 agg ----
    agg_csr_kernel<<<nblk_agg, T>>>(hbuf, hid, b1);

    // ---- layer 2 ----
    gemm_f16_kernel<<<nblk_gemm, T>>>(hid, W2, hbuf);
    agg_csr_kernel<<<nblk_agg, T>>>(hbuf, hid, b2);

    // ---- classifier ----
    cls_f16_kernel<<<nblk_gemm, T>>>(hid, Wl, bl, out);
}